// round 16
// baseline (speedup 1.0000x reference)
#include <cuda_runtime.h>
#include <cuda_fp16.h>
#include <cstdint>
#include <cstddef>

// out = x @ Wv^T + bv.  (Reference's softmax rows sum to 1 => its final
// einsum('btu,btj->btj', weights, v) == v + rounding; Q/K/softmax are dead.)
//
// Single-pass fp16 GEMM M=8192, K=1024, N=64 on portable mma.sync m16n8k16.
// R16: x loads move OFF the SM L1tex fill path (measured ~2.7 TB/s MSHR wall)
// onto the TMA/bulk engine: cp.async.bulk (baseline sm_90 PTX -> UBLKCP) with
// mbarrier completion. MT=16, grid 512: each CTA bulk-copies its whole 64KB
// x tile (16 x 4KB full-row ops), one mbar wait, then computes all 64
// k16-steps in one burst. 8 warps = 2N x 4K-split; W double-buffered in regs
// from L2-hot g_wf (distance-2). ~66KB smem -> 2-3 CTAs/SM overlap.

#define NEMB    1024
#define NH      64
#define MT      16
#define THREADS 256
#define GRID    512              // 8192 / 16
#define XPW     1028             // words per smem x row (4112B, 16B-aligned)
#define XROW_B  4112
#define MBAR_OFF (MT * XROW_B)   // 65792
#define SMEM_BYTES (MBAR_OFF + 16)

// W fragments (layout proven R9-R15): g_wf[s*128 + (wn*2+p)*32 + lane]
__device__ uint4 g_wf[8192];

__global__ void wconv(const float* __restrict__ W)
{
    int id   = blockIdx.x * blockDim.x + threadIdx.x;   // 0..8191
    int lane = id & 31;
    int p    = (id >> 5) & 1;
    int wn   = (id >> 6) & 1;
    int s    = id >> 7;
    int k    = s * 16 + (lane & 3) * 2;
    int j0   = wn * 4 + p * 2;
    uint4 o;
#pragma unroll
    for (int jj = 0; jj < 2; jj++) {
        int n = (j0 + jj) * 8 + (lane >> 2);
        const float* ptr = W + (size_t)n * NEMB + k;
        __half2 h0 = __float22half2_rn(make_float2(ptr[0], ptr[1]));
        __half2 h1 = __float22half2_rn(make_float2(ptr[8], ptr[9]));
        if (jj == 0) { o.x = *(uint32_t*)&h0; o.y = *(uint32_t*)&h1; }
        else         { o.z = *(uint32_t*)&h0; o.w = *(uint32_t*)&h1; }
    }
    g_wf[id] = o;
}

__device__ __forceinline__ void mma16816(float* c,
                                         uint32_t a0, uint32_t a1, uint32_t a2, uint32_t a3,
                                         uint32_t b0, uint32_t b1)
{
    asm volatile(
        "mma.sync.aligned.m16n8k16.row.col.f32.f16.f16.f32 "
        "{%0,%1,%2,%3}, {%4,%5,%6,%7}, {%8,%9}, {%0,%1,%2,%3};"
        : "+f"(c[0]), "+f"(c[1]), "+f"(c[2]), "+f"(c[3])
        : "r"(a0), "r"(a1), "r"(a2), "r"(a3), "r"(b0), "r"(b1));
}

__device__ __forceinline__ uint32_t packh2(float a, float b)
{
    __half2 h = __float22half2_rn(make_float2(a, b));
    return *(uint32_t*)&h;
}

__device__ __forceinline__ void bulk_cp(uint32_t dst, const void* src,
                                        uint32_t bytes, uint32_t mbar)
{
    asm volatile(
        "cp.async.bulk.shared::cluster.global.mbarrier::complete_tx::bytes "
        "[%0], [%1], %2, [%3];"
        :: "r"(dst), "l"(src), "r"(bytes), "r"(mbar) : "memory");
}

__shared__ float bias_s[NH];
extern __shared__ char smem[];

__global__ void __launch_bounds__(THREADS)
vproj(const float* __restrict__ x, const float* __restrict__ bv,
      float* __restrict__ out)
{
    const int t   = threadIdx.x;
    const int wid = t >> 5;
    const int lid = t & 31;
    const int kh  = wid >> 1;         // K quarter: k16-steps kh*16 .. kh*16+15
    const int wn  = wid & 1;          // N half (32 cols = 4 n-tiles)
    const int rowbase = blockIdx.x * MT;

    float* xsm = (float*)smem;
    const uint32_t xsm_s = (uint32_t)__cvta_generic_to_shared(xsm);
    const uint32_t mbar  = xsm_s + MBAR_OFF;

    if (t < 16) ((float4*)bias_s)[t] = ((const float4*)bv)[t];

    if (t == 0)
        asm volatile("mbarrier.init.shared.b64 [%0], 1;" :: "r"(mbar) : "memory");
    __syncthreads();

    // ---- issue the whole x tile on the bulk engine (16 x 4KB row copies) ----
    if (wid == 0) {
        if (lid == 0)
            asm volatile("mbarrier.arrive.expect_tx.shared.b64 _, [%0], %1;"
                         :: "r"(mbar), "r"(MT * 4096u) : "memory");
        __syncwarp();
        if (lid < MT)
            bulk_cp(xsm_s + (uint32_t)lid * XROW_B,
                    x + (size_t)(rowbase + lid) * NEMB, 4096u, mbar);
    }

    // ---- W register prefetch (L2-hot), groups of 2 k16-steps, distance 2 ----
    const int wbase  = wn * 64 + lid;
    const int khbase = kh * 16;
    uint4 w0[2][2], w1[2][2];
#define WL2(b, g)                                                           \
    {                                                                       \
        if ((g) < 8) {                                                      \
            const int s0_ = khbase + (g) * 2;                               \
            w0[b][0] = g_wf[s0_ * 128 + wbase];                             \
            w1[b][0] = g_wf[s0_ * 128 + wbase + 32];                        \
            w0[b][1] = g_wf[(s0_ + 1) * 128 + wbase];                       \
            w1[b][1] = g_wf[(s0_ + 1) * 128 + wbase + 32];                  \
        }                                                                   \
    }
    WL2(0, 0) WL2(1, 1)

    float acc[4][4];
#pragma unroll
    for (int j = 0; j < 4; j++)
#pragma unroll
        for (int e = 0; e < 4; e++) acc[j][e] = 0.0f;

    // ---- wait for the tile ----
    {
        asm volatile(
            "{\n\t"
            ".reg .pred P1;\n\t"
            "WL_%=:\n\t"
            "mbarrier.try_wait.parity.acquire.cta.shared::cta.b64 P1, [%0], 0, 0x989680;\n\t"
            "@P1 bra.uni WD_%=;\n\t"
            "bra.uni WL_%=;\n\t"
            "WD_%=:\n\t"
            "}"
            :: "r"(mbar) : "memory");
    }

    // ---- compute all 16 of this warp's k16-steps ----
    const int abase = (lid >> 2) * XPW + (lid & 3) * 2;

#define XFRAG(sl, sabs)                                                     \
    {                                                                       \
        const float* ap = xsm + abase + (sabs) * 16;                        \
        float2 f0 = *(const float2*)ap;                                     \
        float2 f1 = *(const float2*)(ap + 8 * XPW);                         \
        float2 f2 = *(const float2*)(ap + 8);                               \
        float2 f3 = *(const float2*)(ap + 8 * XPW + 8);                     \
        a0[sl] = packh2(f0.x, f0.y);                                        \
        a1[sl] = packh2(f1.x, f1.y);                                        \
        a2[sl] = packh2(f2.x, f2.y);                                        \
        a3[sl] = packh2(f3.x, f3.y);                                        \
    }
#define DO4(sl, b, jj)                                                      \
    {                                                                       \
        mma16816(acc[0], a0[sl], a1[sl], a2[sl], a3[sl], w0[b][jj].x, w0[b][jj].y); \
        mma16816(acc[1], a0[sl], a1[sl], a2[sl], a3[sl], w0[b][jj].z, w0[b][jj].w); \
        mma16816(acc[2], a0[sl], a1[sl], a2[sl], a3[sl], w1[b][jj].x, w1[b][jj].y); \
        mma16816(acc[3], a0[sl], a1[sl], a2[sl], a3[sl], w1[b][jj].z, w1[b][jj].w); \
    }
    // compute group g from buffer g&1, then refill that buffer with group g+2
#define GRP(g)                                                              \
    {                                                                       \
        uint32_t a0[2], a1[2], a2[2], a3[2];                                \
        XFRAG(0, khbase + (g) * 2)                                          \
        XFRAG(1, khbase + (g) * 2 + 1)                                      \
        DO4(0, (g) & 1, 0)                                                  \
        DO4(1, (g) & 1, 1)                                                  \
        WL2((g) & 1, (g) + 2)                                               \
    }

    GRP(0) GRP(1) GRP(2) GRP(3) GRP(4) GRP(5) GRP(6) GRP(7)

    // ---- K-split reduction (4 partials) + epilogue ----
    __syncthreads();                 // xsm reusable as scratch
    float* red = xsm;
    if (kh > 0) {
        const int rbase = (((kh - 1) * 2 + wn) * 32 + lid) * 20;
#pragma unroll
        for (int j = 0; j < 4; j++)
            *(float4*)(red + rbase + j * 4) = *(float4*)acc[j];
    }
    __syncthreads();
    if (kh == 0) {
        const int orow = rowbase + (lid >> 2);
#pragma unroll
        for (int j = 0; j < 4; j++) {
            float4 s1 = *(float4*)(red + ((0 * 2 + wn) * 32 + lid) * 20 + j * 4);
            float4 s2 = *(float4*)(red + ((1 * 2 + wn) * 32 + lid) * 20 + j * 4);
            float4 s3 = *(float4*)(red + ((2 * 2 + wn) * 32 + lid) * 20 + j * 4);
            const int col = wn * 32 + j * 8 + ((lid & 3) << 1);
            const float b0 = bias_s[col], b1 = bias_s[col + 1];
            float2 lo = make_float2(acc[j][0] + s1.x + s2.x + s3.x + b0,
                                    acc[j][1] + s1.y + s2.y + s3.y + b1);
            float2 hi = make_float2(acc[j][2] + s1.z + s2.z + s3.z + b0,
                                    acc[j][3] + s1.w + s2.w + s3.w + b1);
            *(float2*)(out + (size_t)orow * NH + col)       = lo;
            *(float2*)(out + (size_t)(orow + 8) * NH + col) = hi;
        }
    }
#undef WL2
#undef XFRAG
#undef DO4
#undef GRP
}

extern "C" void kernel_launch(void* const* d_in, const int* in_sizes, int n_in,
                              void* d_out, int out_size)
{
    const float* x  = (const float*)d_in[0];
    const float* Wv = (const float*)d_in[5];
    const float* bv = (const float*)d_in[6];

    cudaFuncSetAttribute(vproj, cudaFuncAttributeMaxDynamicSharedMemorySize, SMEM_BYTES);
    wconv<<<32, 256>>>(Wv);
    vproj<<<GRID, THREADS, SMEM_BYTES>>>(x, bv, (float*)d_out);
}